// round 3
// baseline (speedup 1.0000x reference)
#include <cuda_runtime.h>
#include <cstdint>

#define BB 16
#define SS 4096
#define SK 4097
#define DD 1024
#define HH 16
#define HD 64
#define SP 4112

typedef unsigned long long u64;

__device__ __forceinline__ void ffma2(u64& acc, u64 a, u64 b) {
    asm("fma.rn.f32x2 %0, %1, %2, %0;" : "+l"(acc) : "l"(a), "l"(b));
}
__device__ __forceinline__ float2 unpack2(u64 v) {
    float2 f; asm("mov.b64 {%0, %1}, %2;" : "=f"(f.x), "=f"(f.y) : "l"(v)); return f;
}

// ---------------- scratch ----------------
__device__ float g_q[BB * DD];
__device__ float g_R[BB * HH * DD];
__device__ float g_sc[BB * HH * SP];
__device__ float g_W[BB * HH * DD];
__device__ float g_ctx[BB * DD];

// ---------------- A1: q = (query @ Wq^T + bq) * hd^-0.5 ----------------
__global__ void k_qproj(const float* __restrict__ query,
                        const float* __restrict__ w_in,
                        const float* __restrict__ b_in) {
    int o = blockIdx.x * 8 + (threadIdx.x >> 5);
    int lane = threadIdx.x & 31;
    int b = o & 15, i = o >> 4;
    const float* qr = query + b * DD;
    const float* wr = w_in + (size_t)i * DD;
    float acc = 0.f;
    #pragma unroll
    for (int k = lane * 4; k < DD; k += 128) {
        float4 a = *(const float4*)(qr + k);
        float4 w = *(const float4*)(wr + k);
        acc += a.x * w.x + a.y * w.y + a.z * w.z + a.w * w.w;
    }
    #pragma unroll
    for (int off = 16; off; off >>= 1) acc += __shfl_down_sync(0xffffffffu, acc, off);
    if (lane == 0) g_q[b * DD + i] = (acc + b_in[i]) * 0.125f;
}

// ---------------- A2: r[b][h][d]; also zero g_W ----------------
__global__ void k_rproj(const float* __restrict__ w_in) {
    int b = blockIdx.x >> 4, h = blockIdx.x & 15;
    int t = threadIdx.x;
    __shared__ float qh[HD];
    if (t < HD) qh[t] = g_q[b * DD + h * HD + t];
    *(float4*)&g_W[(b * HH + h) * DD + 4 * t] = make_float4(0.f, 0.f, 0.f, 0.f);
    __syncthreads();
    float4 acc = make_float4(0.f, 0.f, 0.f, 0.f);
    const float* wk = w_in + (size_t)(DD + h * HD) * DD + 4 * t;
    #pragma unroll 8
    for (int j = 0; j < HD; j++) {
        float4 w = *(const float4*)(wk + (size_t)j * DD);
        float qv = qh[j];
        acc.x += w.x * qv; acc.y += w.y * qv; acc.z += w.z * qv; acc.w += w.w * qv;
    }
    *(float4*)&g_R[(b * HH + h) * DD + 4 * t] = acc;
}

// ---------------- B: fused copy-K + scores (FFMA2 mainloop) ----------------
// grid (33,16); 128 threads. s-tile 128, d-chunk 64. Pitch 70: 8B aligned rows,
// conflict-free 64-bit LDS phases.
__global__ void __launch_bounds__(128) k_scores_copyk(
    const float* __restrict__ past_key, const float* __restrict__ key,
    float* __restrict__ comb_key) {
    const int b = blockIdx.y;
    const int s0 = blockIdx.x * 128;
    const int t = threadIdx.x;
    __shared__ float Rt[HH][70];
    __shared__ float CKt[128][70];
    u64 acc2[4][4] = {};
    const int hgrp = t >> 5, sgrp = t & 31;
    const bool fast = (s0 + 128 <= SS);

    for (int dc = 0; dc < DD; dc += 64) {
        #pragma unroll
        for (int p = 0; p < 2; p++) {
            int idx = p * 128 + t;
            int row = idx >> 4, c4 = (idx & 15) * 4;
            float4 v = *(const float4*)&g_R[(size_t)(b * HH + row) * DD + dc + c4];
            *(float2*)&Rt[row][c4]     = make_float2(v.x, v.y);
            *(float2*)&Rt[row][c4 + 2] = make_float2(v.z, v.w);
        }
        #pragma unroll
        for (int p = 0; p < 16; p++) {
            int row = p * 8 + (t >> 4);
            int c4 = (t & 15) * 4;
            int s = s0 + row;
            float4 v;
            if (fast || s < SS) {
                v = __ldcs((const float4*)&past_key[((size_t)b * SS + s) * DD + dc + c4]);
                __stcs((float4*)&comb_key[((size_t)b * SK + s) * DD + dc + c4], v);
            } else if (s == SS) {
                v = *(const float4*)&key[b * DD + dc + c4];
                __stcs((float4*)&comb_key[((size_t)b * SK + s) * DD + dc + c4], v);
            } else {
                v = make_float4(0.f, 0.f, 0.f, 0.f);
            }
            *(float2*)&CKt[row][c4]     = make_float2(v.x, v.y);
            *(float2*)&CKt[row][c4 + 2] = make_float2(v.z, v.w);
        }
        __syncthreads();
        #pragma unroll 4
        for (int dd = 0; dd < 64; dd += 2) {
            u64 r0 = *(const u64*)&Rt[hgrp * 4 + 0][dd];
            u64 r1 = *(const u64*)&Rt[hgrp * 4 + 1][dd];
            u64 r2 = *(const u64*)&Rt[hgrp * 4 + 2][dd];
            u64 r3 = *(const u64*)&Rt[hgrp * 4 + 3][dd];
            u64 c0 = *(const u64*)&CKt[sgrp][dd];
            u64 c1 = *(const u64*)&CKt[sgrp + 32][dd];
            u64 c2 = *(const u64*)&CKt[sgrp + 64][dd];
            u64 c3 = *(const u64*)&CKt[sgrp + 96][dd];
            ffma2(acc2[0][0], r0, c0); ffma2(acc2[0][1], r0, c1); ffma2(acc2[0][2], r0, c2); ffma2(acc2[0][3], r0, c3);
            ffma2(acc2[1][0], r1, c0); ffma2(acc2[1][1], r1, c1); ffma2(acc2[1][2], r1, c2); ffma2(acc2[1][3], r1, c3);
            ffma2(acc2[2][0], r2, c0); ffma2(acc2[2][1], r2, c1); ffma2(acc2[2][2], r2, c2); ffma2(acc2[2][3], r2, c3);
            ffma2(acc2[3][0], r3, c0); ffma2(acc2[3][1], r3, c1); ffma2(acc2[3][2], r3, c2); ffma2(acc2[3][3], r3, c3);
        }
        __syncthreads();
    }
    #pragma unroll
    for (int i = 0; i < 4; i++) {
        int h = hgrp * 4 + i;
        #pragma unroll
        for (int j = 0; j < 4; j++) {
            int s = s0 + sgrp + 32 * j;
            if (s < SK) {
                float2 f = unpack2(acc2[i][j]);
                g_sc[(size_t)(b * HH + h) * SP + s] = f.x + f.y;
            }
        }
    }
}

// ---------------- C: softmax, 512 threads ----------------
__global__ void k_softmax() {
    int b = blockIdx.x >> 4, h = blockIdx.x & 15;
    float* sc = g_sc + (size_t)(b * HH + h) * SP;
    __shared__ float buf[SK];
    __shared__ float red[512];
    int t = threadIdx.x;
    float m = -1e30f;
    for (int i = t; i < SK; i += 512) { float v = sc[i]; buf[i] = v; m = fmaxf(m, v); }
    red[t] = m; __syncthreads();
    for (int o = 256; o; o >>= 1) { if (t < o) red[t] = fmaxf(red[t], red[t + o]); __syncthreads(); }
    m = red[0]; __syncthreads();
    float s = 0.f;
    for (int i = t; i < SK; i += 512) { float e = __expf(buf[i] - m); buf[i] = e; s += e; }
    red[t] = s; __syncthreads();
    for (int o = 256; o; o >>= 1) { if (t < o) red[t] += red[t + o]; __syncthreads(); }
    float inv = 1.f / red[0];
    __syncthreads();
    for (int i = t; i < SK; i += 512) sc[i] = buf[i] * inv;
}

// ---------------- D: fused copy-V + weighted sum (FFMA2 mainloop) -----------
// grid (17,16); 256 threads. Attn pre-duplicated as float2 in smem; cv loaded
// as packed (x,y)/(z,w) u64 pairs straight from the 16B global load.
__global__ void __launch_bounds__(256) k_wsum_copyv(
    const float* __restrict__ past_value, const float* __restrict__ value,
    float* __restrict__ comb_value) {
    int b = blockIdx.y;
    int s0 = blockIdx.x * 256;
    int t = threadIdx.x;
    __shared__ float2 At2[HH][256];
    #pragma unroll
    for (int p = 0; p < 16; p++) {
        int idx = p * 256 + t;
        int h = idx >> 8, sl = idx & 255;
        int s = s0 + sl;
        float v = (s < SK) ? g_sc[(size_t)(b * HH + h) * SP + s] : 0.f;
        At2[h][sl] = make_float2(v, v);
    }
    __syncthreads();
    u64 axy[HH], azw[HH];
    #pragma unroll
    for (int h = 0; h < HH; h++) { axy[h] = 0ull; azw[h] = 0ull; }
    const int d = 4 * t;
    const bool fast = (s0 + 256 <= SS);

    for (int sg = 0; sg < 256; sg += 4) {
        u64 cx[4], cz[4];
        #pragma unroll
        for (int j = 0; j < 4; j++) {
            int s = s0 + sg + j;
            longlong2 v;
            if (fast || s < SS) {
                v = __ldcs((const longlong2*)&past_value[((size_t)b * SS + s) * DD + d]);
                __stcs((longlong2*)&comb_value[((size_t)b * SK + s) * DD + d], v);
            } else if (s == SS) {
                v = *(const longlong2*)&value[b * DD + d];
                __stcs((longlong2*)&comb_value[((size_t)b * SK + s) * DD + d], v);
            } else {
                v.x = 0; v.y = 0;
            }
            cx[j] = (u64)v.x; cz[j] = (u64)v.y;
        }
        #pragma unroll
        for (int h = 0; h < HH; h++) {
            #pragma unroll
            for (int j = 0; j < 4; j++) {
                u64 a = *(const u64*)&At2[h][sg + j];
                ffma2(axy[h], a, cx[j]);
                ffma2(azw[h], a, cz[j]);
            }
        }
    }
    #pragma unroll
    for (int h = 0; h < HH; h++) {
        float2 xy = unpack2(axy[h]);
        float2 zw = unpack2(azw[h]);
        float* w = &g_W[(size_t)(b * HH + h) * DD + d];
        atomicAdd(w + 0, xy.x);
        atomicAdd(w + 1, xy.y);
        atomicAdd(w + 2, zw.x);
        atomicAdd(w + 3, zw.y);
    }
}

// ---------------- E1: ctx ----------------
__global__ void k_ctxproj(const float* __restrict__ w_in,
                          const float* __restrict__ b_in) {
    int o = blockIdx.x * 8 + (threadIdx.x >> 5);
    int lane = threadIdx.x & 31;
    int b = o & 15, i = o >> 4, h = i >> 6;
    const float* wv = w_in + (size_t)(2 * DD + i) * DD;
    const float* Wb = g_W + (size_t)(b * HH + h) * DD;
    float acc = 0.f;
    #pragma unroll
    for (int k = lane * 4; k < DD; k += 128) {
        float4 a = *(const float4*)(wv + k);
        float4 w = *(const float4*)(Wb + k);
        acc += a.x * w.x + a.y * w.y + a.z * w.z + a.w * w.w;
    }
    #pragma unroll
    for (int off = 16; off; off >>= 1) acc += __shfl_down_sync(0xffffffffu, acc, off);
    if (lane == 0) g_ctx[b * DD + i] = acc + b_in[2 * DD + i];
}

// ---------------- E2: out ----------------
__global__ void k_outproj(const float* __restrict__ w_out,
                          const float* __restrict__ b_out,
                          float* __restrict__ out) {
    int o = blockIdx.x * 8 + (threadIdx.x >> 5);
    int lane = threadIdx.x & 31;
    int b = o & 15, i = o >> 4;
    const float* wr = w_out + (size_t)i * DD;
    const float* cx = g_ctx + b * DD;
    float acc = 0.f;
    #pragma unroll
    for (int k = lane * 4; k < DD; k += 128) {
        float4 a = *(const float4*)(wr + k);
        float4 w = *(const float4*)(cx + k);
        acc += a.x * w.x + a.y * w.y + a.z * w.z + a.w * w.w;
    }
    #pragma unroll
    for (int off = 16; off; off >>= 1) acc += __shfl_down_sync(0xffffffffu, acc, off);
    if (lane == 0) out[b * DD + i] = acc + b_out[i];
}

// ---------------- launch ----------------
extern "C" void kernel_launch(void* const* d_in, const int* in_sizes, int n_in,
                              void* d_out, int out_size) {
    const float* query      = (const float*)d_in[0];
    const float* key        = (const float*)d_in[1];
    const float* value      = (const float*)d_in[2];
    const float* past_key   = (const float*)d_in[3];
    const float* past_value = (const float*)d_in[4];
    const float* w_in       = (const float*)d_in[5];
    const float* b_in       = (const float*)d_in[6];
    const float* w_out      = (const float*)d_in[7];
    const float* b_out      = (const float*)d_in[8];

    float* out        = (float*)d_out;
    float* comb_key   = out + (size_t)BB * DD;
    float* comb_value = comb_key + (size_t)BB * SK * DD;

    k_qproj<<<2048, 256>>>(query, w_in, b_in);
    k_rproj<<<256, 256>>>(w_in);
    k_scores_copyk<<<dim3(33, 16), 128>>>(past_key, key, comb_key);
    k_softmax<<<256, 512>>>();
    k_wsum_copyv<<<dim3(17, 16), 256>>>(past_value, value, comb_value);
    k_ctxproj<<<2048, 256>>>(w_in, b_in);
    k_outproj<<<2048, 256>>>(w_out, b_out, out);
}

// round 5
// speedup vs baseline: 1.1447x; 1.1447x over previous
#include <cuda_runtime.h>
#include <cstdint>

#define BB 16
#define SS 4096
#define SK 4097
#define DD 1024
#define HH 16
#define HD 64
#define SP 4112

typedef unsigned long long u64;

__device__ __forceinline__ void ffma2(u64& acc, u64 a, u64 b) {
    asm("fma.rn.f32x2 %0, %1, %2, %0;" : "+l"(acc) : "l"(a), "l"(b));
}
__device__ __forceinline__ float2 unpack2(u64 v) {
    float2 f; asm("mov.b64 {%0, %1}, %2;" : "=f"(f.x), "=f"(f.y) : "l"(v)); return f;
}
__device__ __forceinline__ u64 pack2(float x, float y) {
    u64 v; asm("mov.b64 %0, {%1, %2};" : "=l"(v) : "f"(x), "f"(y)); return v;
}

// ---------------- scratch ----------------
__device__ float g_q[BB * DD];
__device__ float g_R[BB * HH * DD];
__device__ float g_sc[BB * HH * SP];
__device__ float g_W[BB * HH * DD];
__device__ float g_ctx[BB * DD];
__device__ float g_dummy[32];

// ---------------- dummy (shifts ncu capture window onto k_scores_copyk) ----
__global__ void k_dummy() { g_dummy[threadIdx.x] = 0.f; }

// ---------------- A1: q = (query @ Wq^T + bq) * hd^-0.5 ----------------
__global__ void k_qproj(const float* __restrict__ query,
                        const float* __restrict__ w_in,
                        const float* __restrict__ b_in) {
    int o = blockIdx.x * 8 + (threadIdx.x >> 5);
    int lane = threadIdx.x & 31;
    int b = o & 15, i = o >> 4;
    const float* qr = query + b * DD;
    const float* wr = w_in + (size_t)i * DD;
    float acc = 0.f;
    #pragma unroll
    for (int k = lane * 4; k < DD; k += 128) {
        float4 a = *(const float4*)(qr + k);
        float4 w = *(const float4*)(wr + k);
        acc += a.x * w.x + a.y * w.y + a.z * w.z + a.w * w.w;
    }
    #pragma unroll
    for (int off = 16; off; off >>= 1) acc += __shfl_down_sync(0xffffffffu, acc, off);
    if (lane == 0) g_q[b * DD + i] = (acc + b_in[i]) * 0.125f;
}

// ---------------- A2: r[b][h][d]; also zero g_W ----------------
__global__ void k_rproj(const float* __restrict__ w_in) {
    int b = blockIdx.x >> 4, h = blockIdx.x & 15;
    int t = threadIdx.x;
    __shared__ float qh[HD];
    if (t < HD) qh[t] = g_q[b * DD + h * HD + t];
    *(float4*)&g_W[(b * HH + h) * DD + 4 * t] = make_float4(0.f, 0.f, 0.f, 0.f);
    __syncthreads();
    float4 acc = make_float4(0.f, 0.f, 0.f, 0.f);
    const float* wk = w_in + (size_t)(DD + h * HD) * DD + 4 * t;
    #pragma unroll 8
    for (int j = 0; j < HD; j++) {
        float4 w = *(const float4*)(wk + (size_t)j * DD);
        float qv = qh[j];
        acc.x += w.x * qv; acc.y += w.y * qv; acc.z += w.z * qv; acc.w += w.w * qv;
    }
    *(float4*)&g_R[(b * HH + h) * DD + 4 * t] = acc;
}

// ---------------- B: fused copy-K + scores, row-per-thread streaming --------
// grid (17,16); 256 threads. Thread owns s-row; R staged in smem in 256-d
// chunks; all R reads are warp-uniform broadcasts (no conflicts possible).
// FFMA2 halves the FMA issue count; copy fused with the score dot.
__global__ void __launch_bounds__(256) k_scores_copyk(
    const float* __restrict__ past_key, const float* __restrict__ key,
    float* __restrict__ comb_key) {
    const int b = blockIdx.y;
    const int t = threadIdx.x;
    const int s = blockIdx.x * 256 + t;
    __shared__ float Rt[HH][256];
    u64 acc[HH];
    #pragma unroll
    for (int h = 0; h < HH; h++) acc[h] = 0ull;
    const bool valid = s < SK;
    const float* src = (s < SS) ? past_key + ((size_t)b * SS + s) * DD
                                : key + (size_t)b * DD;
    float* dst = comb_key + ((size_t)b * SK + s) * DD;

    for (int dc = 0; dc < DD; dc += 256) {
        __syncthreads();
        #pragma unroll
        for (int p = 0; p < 4; p++) {
            int idx = p * 256 + t;
            int row = idx >> 6, c = (idx & 63) * 4;
            *(float4*)&Rt[row][c] =
                *(const float4*)&g_R[(size_t)(b * HH + row) * DD + dc + c];
        }
        __syncthreads();
        if (valid) {
            #pragma unroll 4
            for (int j = 0; j < 256; j += 4) {
                float4 v = *(const float4*)(src + dc + j);
                *(float4*)(dst + dc + j) = v;
                u64 vxy = pack2(v.x, v.y);
                u64 vzw = pack2(v.z, v.w);
                #pragma unroll
                for (int h = 0; h < HH; h++) {
                    float4 r = *(const float4*)&Rt[h][j];   // warp broadcast
                    ffma2(acc[h], vxy, pack2(r.x, r.y));
                    ffma2(acc[h], vzw, pack2(r.z, r.w));
                }
            }
        }
    }
    if (valid) {
        #pragma unroll
        for (int h = 0; h < HH; h++) {
            float2 f = unpack2(acc[h]);
            g_sc[(size_t)(b * HH + h) * SP + s] = f.x + f.y;
        }
    }
}

// ---------------- C: softmax, 512 threads ----------------
__global__ void k_softmax() {
    int b = blockIdx.x >> 4, h = blockIdx.x & 15;
    float* sc = g_sc + (size_t)(b * HH + h) * SP;
    __shared__ float buf[SK];
    __shared__ float red[512];
    int t = threadIdx.x;
    float m = -1e30f;
    for (int i = t; i < SK; i += 512) { float v = sc[i]; buf[i] = v; m = fmaxf(m, v); }
    red[t] = m; __syncthreads();
    for (int o = 256; o; o >>= 1) { if (t < o) red[t] = fmaxf(red[t], red[t + o]); __syncthreads(); }
    m = red[0]; __syncthreads();
    float s = 0.f;
    for (int i = t; i < SK; i += 512) { float e = __expf(buf[i] - m); buf[i] = e; s += e; }
    red[t] = s; __syncthreads();
    for (int o = 256; o; o >>= 1) { if (t < o) red[t] += red[t + o]; __syncthreads(); }
    float inv = 1.f / red[0];
    __syncthreads();
    for (int i = t; i < SK; i += 512) sc[i] = buf[i] * inv;
}

// ---------------- D: fused copy-V + weighted sum (R2 version, known good) ---
__global__ void __launch_bounds__(256) k_wsum_copyv(
    const float* __restrict__ past_value, const float* __restrict__ value,
    float* __restrict__ comb_value) {
    int b = blockIdx.y;
    int s0 = blockIdx.x * 256;
    int t = threadIdx.x;
    __shared__ float At[HH][256];
    #pragma unroll
    for (int p = 0; p < 16; p++) {
        int idx = p * 256 + t;
        int h = idx >> 8, sl = idx & 255;
        int s = s0 + sl;
        At[h][sl] = (s < SK) ? g_sc[(size_t)(b * HH + h) * SP + s] : 0.f;
    }
    __syncthreads();
    float4 acc[HH];
    #pragma unroll
    for (int h = 0; h < HH; h++) acc[h] = make_float4(0.f, 0.f, 0.f, 0.f);
    const int d = 4 * t;
    const bool fast = (s0 + 256 <= SS);

    for (int sg = 0; sg < 256; sg += 4) {
        float4 cv[4];
        #pragma unroll
        for (int j = 0; j < 4; j++) {
            int s = s0 + sg + j;
            if (fast || s < SS) {
                cv[j] = *(const float4*)&past_value[((size_t)b * SS + s) * DD + d];
                *(float4*)&comb_value[((size_t)b * SK + s) * DD + d] = cv[j];
            } else if (s == SS) {
                cv[j] = *(const float4*)&value[b * DD + d];
                *(float4*)&comb_value[((size_t)b * SK + s) * DD + d] = cv[j];
            } else {
                cv[j] = make_float4(0.f, 0.f, 0.f, 0.f);
            }
        }
        #pragma unroll
        for (int h = 0; h < HH; h++) {
            float4 a = *(const float4*)&At[h][sg];
            acc[h].x += a.x * cv[0].x + a.y * cv[1].x + a.z * cv[2].x + a.w * cv[3].x;
            acc[h].y += a.x * cv[0].y + a.y * cv[1].y + a.z * cv[2].y + a.w * cv[3].y;
            acc[h].z += a.x * cv[0].z + a.y * cv[1].z + a.z * cv[2].z + a.w * cv[3].z;
            acc[h].w += a.x * cv[0].w + a.y * cv[1].w + a.z * cv[2].w + a.w * cv[3].w;
        }
    }
    #pragma unroll
    for (int h = 0; h < HH; h++) {
        float* w = &g_W[(size_t)(b * HH + h) * DD + d];
        atomicAdd(w + 0, acc[h].x);
        atomicAdd(w + 1, acc[h].y);
        atomicAdd(w + 2, acc[h].z);
        atomicAdd(w + 3, acc[h].w);
    }
}

// ---------------- E1: ctx ----------------
__global__ void k_ctxproj(const float* __restrict__ w_in,
                          const float* __restrict__ b_in) {
    int o = blockIdx.x * 8 + (threadIdx.x >> 5);
    int lane = threadIdx.x & 31;
    int b = o & 15, i = o >> 4, h = i >> 6;
    const float* wv = w_in + (size_t)(2 * DD + i) * DD;
    const float* Wb = g_W + (size_t)(b * HH + h) * DD;
    float acc = 0.f;
    #pragma unroll
    for (int k = lane * 4; k < DD; k += 128) {
        float4 a = *(const float4*)(wv + k);
        float4 w = *(const float4*)(Wb + k);
        acc += a.x * w.x + a.y * w.y + a.z * w.z + a.w * w.w;
    }
    #pragma unroll
    for (int off = 16; off; off >>= 1) acc += __shfl_down_sync(0xffffffffu, acc, off);
    if (lane == 0) g_ctx[b * DD + i] = acc + b_in[2 * DD + i];
}

// ---------------- E2: out ----------------
__global__ void k_outproj(const float* __restrict__ w_out,
                          const float* __restrict__ b_out,
                          float* __restrict__ out) {
    int o = blockIdx.x * 8 + (threadIdx.x >> 5);
    int lane = threadIdx.x & 31;
    int b = o & 15, i = o >> 4;
    const float* wr = w_out + (size_t)i * DD;
    const float* cx = g_ctx + b * DD;
    float acc = 0.f;
    #pragma unroll
    for (int k = lane * 4; k < DD; k += 128) {
        float4 a = *(const float4*)(wr + k);
        float4 w = *(const float4*)(cx + k);
        acc += a.x * w.x + a.y * w.y + a.z * w.z + a.w * w.w;
    }
    #pragma unroll
    for (int off = 16; off; off >>= 1) acc += __shfl_down_sync(0xffffffffu, acc, off);
    if (lane == 0) out[b * DD + i] = acc + b_out[i];
}

// ---------------- launch ----------------
extern "C" void kernel_launch(void* const* d_in, const int* in_sizes, int n_in,
                              void* d_out, int out_size) {
    const float* query      = (const float*)d_in[0];
    const float* key        = (const float*)d_in[1];
    const float* value      = (const float*)d_in[2];
    const float* past_key   = (const float*)d_in[3];
    const float* past_value = (const float*)d_in[4];
    const float* w_in       = (const float*)d_in[5];
    const float* b_in       = (const float*)d_in[6];
    const float* w_out      = (const float*)d_in[7];
    const float* b_out      = (const float*)d_in[8];

    float* out        = (float*)d_out;
    float* comb_key   = out + (size_t)BB * DD;
    float* comb_value = comb_key + (size_t)BB * SK * DD;

    k_dummy<<<1, 32>>>();
    k_qproj<<<2048, 256>>>(query, w_in, b_in);
    k_rproj<<<256, 256>>>(w_in);
    k_scores_copyk<<<dim3(17, 16), 256>>>(past_key, key, comb_key);
    k_softmax<<<256, 512>>>();
    k_wsum_copyv<<<dim3(17, 16), 256>>>(past_value, value, comb_value);
    k_ctxproj<<<2048, 256>>>(w_in, b_in);
    k_outproj<<<2048, 256>>>(w_out, b_out, out);
}

// round 6
// speedup vs baseline: 1.2457x; 1.0882x over previous
#include <cuda_runtime.h>
#include <cstdint>

#define BB 16
#define SS 4096
#define SK 4097
#define DD 1024
#define HH 16
#define HD 64
#define SP 4112

typedef unsigned long long u64;

__device__ __forceinline__ void ffma2(u64& acc, u64 a, u64 b) {
    asm("fma.rn.f32x2 %0, %1, %2, %0;" : "+l"(acc) : "l"(a), "l"(b));
}
__device__ __forceinline__ float2 unpack2(u64 v) {
    float2 f; asm("mov.b64 {%0, %1}, %2;" : "=f"(f.x), "=f"(f.y) : "l"(v)); return f;
}

// ---------------- scratch ----------------
__device__ float g_q[BB * DD];
__device__ float g_R[BB * HH * DD];
__device__ float g_sc[BB * HH * SP];
__device__ float g_W[BB * HH * DD];
__device__ float g_ctx[BB * DD];
__device__ float g_dummy[32];

__global__ void k_dummy() { g_dummy[threadIdx.x] = 0.f; }

// ---------------- A1: q = (query @ Wq^T + bq) * hd^-0.5 ----------------
__global__ void k_qproj(const float* __restrict__ query,
                        const float* __restrict__ w_in,
                        const float* __restrict__ b_in) {
    int o = blockIdx.x * 8 + (threadIdx.x >> 5);
    int lane = threadIdx.x & 31;
    int b = o & 15, i = o >> 4;
    const float* qr = query + b * DD;
    const float* wr = w_in + (size_t)i * DD;
    float acc = 0.f;
    #pragma unroll
    for (int k = lane * 4; k < DD; k += 128) {
        float4 a = *(const float4*)(qr + k);
        float4 w = *(const float4*)(wr + k);
        acc += a.x * w.x + a.y * w.y + a.z * w.z + a.w * w.w;
    }
    #pragma unroll
    for (int off = 16; off; off >>= 1) acc += __shfl_down_sync(0xffffffffu, acc, off);
    if (lane == 0) g_q[b * DD + i] = (acc + b_in[i]) * 0.125f;
}

// ---------------- A2: r[b][h][d]; also zero g_W ----------------
__global__ void k_rproj(const float* __restrict__ w_in) {
    int b = blockIdx.x >> 4, h = blockIdx.x & 15;
    int t = threadIdx.x;
    __shared__ float qh[HD];
    if (t < HD) qh[t] = g_q[b * DD + h * HD + t];
    *(float4*)&g_W[(b * HH + h) * DD + 4 * t] = make_float4(0.f, 0.f, 0.f, 0.f);
    __syncthreads();
    float4 acc = make_float4(0.f, 0.f, 0.f, 0.f);
    const float* wk = w_in + (size_t)(DD + h * HD) * DD + 4 * t;
    #pragma unroll 8
    for (int j = 0; j < HD; j++) {
        float4 w = *(const float4*)(wk + (size_t)j * DD);
        float qv = qh[j];
        acc.x += w.x * qv; acc.y += w.y * qv; acc.z += w.z * qv; acc.w += w.w * qv;
    }
    *(float4*)&g_R[(b * HH + h) * DD + 4 * t] = acc;
}

// ---------------- B: fused copy-K + scores, coalesced tiled GEMM ------------
// grid (17,16); 128 threads (4 warps). s-tile 256, d-chunk 32.
// Per-thread tile 8h x 4s, acc as f32x2 over dd-pairs (64 regs).
// Warp w: heads (w>>1)*8 .. +7 (warp-uniform -> R reads are broadcasts);
// s index: ((w&1)<<5)|lane + 64j. CK pitch 34: conflict-free LDS.64, 8B aligned.
__global__ void __launch_bounds__(128) k_scores_copyk(
    const float* __restrict__ past_key, const float* __restrict__ key,
    float* __restrict__ comb_key) {
    const int b = blockIdx.y;
    const int s0 = blockIdx.x * 256;
    const int t = threadIdx.x;
    const int warp = t >> 5, lane = t & 31;
    const int hbase = (warp >> 1) * 8;
    const int sgrp = ((warp & 1) << 5) | lane;   // 0..63
    __shared__ float Rt[HH][34];
    __shared__ float CKt[256][34];
    u64 acc[8][4] = {};

    const int lrow = t >> 3;           // 0..15
    const int lc   = (t & 7) * 4;      // 0,4,..28

    for (int dc = 0; dc < DD; dc += 32) {
        __syncthreads();
        // R tile: 16 x 32, one float4 per thread (pitch 34: store as 2x float2)
        {
            float4 v = *(const float4*)&g_R[(size_t)(b * HH + lrow) * DD + dc + lc];
            *(float2*)&Rt[lrow][lc]     = make_float2(v.x, v.y);
            *(float2*)&Rt[lrow][lc + 2] = make_float2(v.z, v.w);
        }
        // CK tile: 256 x 32, coalesced (8 threads x float4 = 128B per row),
        // write-through to comb_key
        #pragma unroll
        for (int p = 0; p < 16; p++) {
            int row = p * 16 + lrow;
            int s = s0 + row;
            float4 v;
            if (s < SS) {
                v = *(const float4*)&past_key[((size_t)b * SS + s) * DD + dc + lc];
                *(float4*)&comb_key[((size_t)b * SK + s) * DD + dc + lc] = v;
            } else if (s == SS) {
                v = *(const float4*)&key[(size_t)b * DD + dc + lc];
                *(float4*)&comb_key[((size_t)b * SK + s) * DD + dc + lc] = v;
            } else {
                v = make_float4(0.f, 0.f, 0.f, 0.f);
            }
            *(float2*)&CKt[row][lc]     = make_float2(v.x, v.y);
            *(float2*)&CKt[row][lc + 2] = make_float2(v.z, v.w);
        }
        __syncthreads();
        // GEMM over this d-chunk: 16 dd-pairs
        #pragma unroll
        for (int dd = 0; dd < 32; dd += 2) {
            u64 r2[8], c2[4];
            #pragma unroll
            for (int i = 0; i < 8; i++) r2[i] = *(const u64*)&Rt[hbase + i][dd];
            #pragma unroll
            for (int j = 0; j < 4; j++) c2[j] = *(const u64*)&CKt[sgrp + 64 * j][dd];
            #pragma unroll
            for (int i = 0; i < 8; i++) {
                #pragma unroll
                for (int j = 0; j < 4; j++) ffma2(acc[i][j], r2[i], c2[j]);
            }
        }
    }
    #pragma unroll
    for (int i = 0; i < 8; i++) {
        #pragma unroll
        for (int j = 0; j < 4; j++) {
            int s = s0 + sgrp + 64 * j;
            if (s < SK) {
                float2 f = unpack2(acc[i][j]);
                g_sc[(size_t)(b * HH + hbase + i) * SP + s] = f.x + f.y;
            }
        }
    }
}

// ---------------- C: softmax, 512 threads ----------------
__global__ void k_softmax() {
    int b = blockIdx.x >> 4, h = blockIdx.x & 15;
    float* sc = g_sc + (size_t)(b * HH + h) * SP;
    __shared__ float buf[SK];
    __shared__ float red[512];
    int t = threadIdx.x;
    float m = -1e30f;
    for (int i = t; i < SK; i += 512) { float v = sc[i]; buf[i] = v; m = fmaxf(m, v); }
    red[t] = m; __syncthreads();
    for (int o = 256; o; o >>= 1) { if (t < o) red[t] = fmaxf(red[t], red[t + o]); __syncthreads(); }
    m = red[0]; __syncthreads();
    float s = 0.f;
    for (int i = t; i < SK; i += 512) { float e = __expf(buf[i] - m); buf[i] = e; s += e; }
    red[t] = s; __syncthreads();
    for (int o = 256; o; o >>= 1) { if (t < o) red[t] += red[t + o]; __syncthreads(); }
    float inv = 1.f / red[0];
    __syncthreads();
    for (int i = t; i < SK; i += 512) sc[i] = buf[i] * inv;
}

// ---------------- D: fused copy-V + weighted sum (R2 version, known good) ---
__global__ void __launch_bounds__(256) k_wsum_copyv(
    const float* __restrict__ past_value, const float* __restrict__ value,
    float* __restrict__ comb_value) {
    int b = blockIdx.y;
    int s0 = blockIdx.x * 256;
    int t = threadIdx.x;
    __shared__ float At[HH][256];
    #pragma unroll
    for (int p = 0; p < 16; p++) {
        int idx = p * 256 + t;
        int h = idx >> 8, sl = idx & 255;
        int s = s0 + sl;
        At[h][sl] = (s < SK) ? g_sc[(size_t)(b * HH + h) * SP + s] : 0.f;
    }
    __syncthreads();
    float4 acc[HH];
    #pragma unroll
    for (int h = 0; h < HH; h++) acc[h] = make_float4(0.f, 0.f, 0.f, 0.f);
    const int d = 4 * t;
    const bool fast = (s0 + 256 <= SS);

    for (int sg = 0; sg < 256; sg += 4) {
        float4 cv[4];
        #pragma unroll
        for (int j = 0; j < 4; j++) {
            int s = s0 + sg + j;
            if (fast || s < SS) {
                cv[j] = *(const float4*)&past_value[((size_t)b * SS + s) * DD + d];
                *(float4*)&comb_value[((size_t)b * SK + s) * DD + d] = cv[j];
            } else if (s == SS) {
                cv[j] = *(const float4*)&value[b * DD + d];
                *(float4*)&comb_value[((size_t)b * SK + s) * DD + d] = cv[j];
            } else {
                cv[j] = make_float4(0.f, 0.f, 0.f, 0.f);
            }
        }
        #pragma unroll
        for (int h = 0; h < HH; h++) {
            float4 a = *(const float4*)&At[h][sg];
            acc[h].x += a.x * cv[0].x + a.y * cv[1].x + a.z * cv[2].x + a.w * cv[3].x;
            acc[h].y += a.x * cv[0].y + a.y * cv[1].y + a.z * cv[2].y + a.w * cv[3].y;
            acc[h].z += a.x * cv[0].z + a.y * cv[1].z + a.z * cv[2].z + a.w * cv[3].z;
            acc[h].w += a.x * cv[0].w + a.y * cv[1].w + a.z * cv[2].w + a.w * cv[3].w;
        }
    }
    #pragma unroll
    for (int h = 0; h < HH; h++) {
        float* w = &g_W[(size_t)(b * HH + h) * DD + d];
        atomicAdd(w + 0, acc[h].x);
        atomicAdd(w + 1, acc[h].y);
        atomicAdd(w + 2, acc[h].z);
        atomicAdd(w + 3, acc[h].w);
    }
}

// ---------------- E1: ctx ----------------
__global__ void k_ctxproj(const float* __restrict__ w_in,
                          const float* __restrict__ b_in) {
    int o = blockIdx.x * 8 + (threadIdx.x >> 5);
    int lane = threadIdx.x & 31;
    int b = o & 15, i = o >> 4, h = i >> 6;
    const float* wv = w_in + (size_t)(2 * DD + i) * DD;
    const float* Wb = g_W + (size_t)(b * HH + h) * DD;
    float acc = 0.f;
    #pragma unroll
    for (int k = lane * 4; k < DD; k += 128) {
        float4 a = *(const float4*)(wv + k);
        float4 w = *(const float4*)(Wb + k);
        acc += a.x * w.x + a.y * w.y + a.z * w.z + a.w * w.w;
    }
    #pragma unroll
    for (int off = 16; off; off >>= 1) acc += __shfl_down_sync(0xffffffffu, acc, off);
    if (lane == 0) g_ctx[b * DD + i] = acc + b_in[2 * DD + i];
}

// ---------------- E2: out ----------------
__global__ void k_outproj(const float* __restrict__ w_out,
                          const float* __restrict__ b_out,
                          float* __restrict__ out) {
    int o = blockIdx.x * 8 + (threadIdx.x >> 5);
    int lane = threadIdx.x & 31;
    int b = o & 15, i = o >> 4;
    const float* wr = w_out + (size_t)i * DD;
    const float* cx = g_ctx + b * DD;
    float acc = 0.f;
    #pragma unroll
    for (int k = lane * 4; k < DD; k += 128) {
        float4 a = *(const float4*)(wr + k);
        float4 w = *(const float4*)(cx + k);
        acc += a.x * w.x + a.y * w.y + a.z * w.z + a.w * w.w;
    }
    #pragma unroll
    for (int off = 16; off; off >>= 1) acc += __shfl_down_sync(0xffffffffu, acc, off);
    if (lane == 0) out[b * DD + i] = acc + b_out[i];
}

// ---------------- launch ----------------
extern "C" void kernel_launch(void* const* d_in, const int* in_sizes, int n_in,
                              void* d_out, int out_size) {
    const float* query      = (const float*)d_in[0];
    const float* key        = (const float*)d_in[1];
    const float* value      = (const float*)d_in[2];
    const float* past_key   = (const float*)d_in[3];
    const float* past_value = (const float*)d_in[4];
    const float* w_in       = (const float*)d_in[5];
    const float* b_in       = (const float*)d_in[6];
    const float* w_out      = (const float*)d_in[7];
    const float* b_out      = (const float*)d_in[8];

    float* out        = (float*)d_out;
    float* comb_key   = out + (size_t)BB * DD;
    float* comb_value = comb_key + (size_t)BB * SK * DD;

    k_dummy<<<1, 32>>>();
    k_qproj<<<2048, 256>>>(query, w_in, b_in);
    k_rproj<<<256, 256>>>(w_in);
    k_scores_copyk<<<dim3(17, 16), 128>>>(past_key, key, comb_key);
    k_softmax<<<256, 512>>>();
    k_wsum_copyv<<<dim3(17, 16), 256>>>(past_value, value, comb_value);
    k_ctxproj<<<2048, 256>>>(w_in, b_in);
    k_outproj<<<2048, 256>>>(w_out, b_out, out);
}

// round 7
// speedup vs baseline: 1.4841x; 1.1914x over previous
#include <cuda_runtime.h>
#include <cstdint>

#define BB 16
#define SS 4096
#define SK 4097
#define DD 1024
#define HH 16
#define HD 64
#define SP 4112

typedef unsigned long long u64;

__device__ __forceinline__ void ffma2(u64& acc, u64 a, u64 b) {
    asm("fma.rn.f32x2 %0, %1, %2, %0;" : "+l"(acc) : "l"(a), "l"(b));
}
__device__ __forceinline__ float2 unpack2(u64 v) {
    float2 f; asm("mov.b64 {%0, %1}, %2;" : "=f"(f.x), "=f"(f.y) : "l"(v)); return f;
}

// ---------------- scratch ----------------
__device__ float g_q[BB * DD];
__device__ float g_R[BB * HH * DD];
__device__ float g_sc[BB * HH * SP];
__device__ float g_W[BB * HH * DD];
__device__ float g_ctx[BB * DD];
__device__ float g_dummy[32];

__global__ void k_dummy() { g_dummy[threadIdx.x] = 0.f; }

// ---------------- A1: q = (query @ Wq^T + bq) * hd^-0.5 ----------------
__global__ void k_qproj(const float* __restrict__ query,
                        const float* __restrict__ w_in,
                        const float* __restrict__ b_in) {
    int o = blockIdx.x * 8 + (threadIdx.x >> 5);
    int lane = threadIdx.x & 31;
    int b = o & 15, i = o >> 4;
    const float* qr = query + b * DD;
    const float* wr = w_in + (size_t)i * DD;
    float acc = 0.f;
    #pragma unroll
    for (int k = lane * 4; k < DD; k += 128) {
        float4 a = *(const float4*)(qr + k);
        float4 w = *(const float4*)(wr + k);
        acc += a.x * w.x + a.y * w.y + a.z * w.z + a.w * w.w;
    }
    #pragma unroll
    for (int off = 16; off; off >>= 1) acc += __shfl_down_sync(0xffffffffu, acc, off);
    if (lane == 0) g_q[b * DD + i] = (acc + b_in[i]) * 0.125f;
}

// ---------------- A2: r[b][h][d]; also zero g_W ----------------
__global__ void k_rproj(const float* __restrict__ w_in) {
    int b = blockIdx.x >> 4, h = blockIdx.x & 15;
    int t = threadIdx.x;
    __shared__ float qh[HD];
    if (t < HD) qh[t] = g_q[b * DD + h * HD + t];
    *(float4*)&g_W[(b * HH + h) * DD + 4 * t] = make_float4(0.f, 0.f, 0.f, 0.f);
    __syncthreads();
    float4 acc = make_float4(0.f, 0.f, 0.f, 0.f);
    const float* wk = w_in + (size_t)(DD + h * HD) * DD + 4 * t;
    #pragma unroll 8
    for (int j = 0; j < HD; j++) {
        float4 w = *(const float4*)(wk + (size_t)j * DD);
        float qv = qh[j];
        acc.x += w.x * qv; acc.y += w.y * qv; acc.z += w.z * qv; acc.w += w.w * qv;
    }
    *(float4*)&g_R[(b * HH + h) * DD + 4 * t] = acc;
}

// ---------------- B: fused copy-K + scores, coalesced tiled GEMM v4 ---------
// grid (17,16); 256 threads (8 warps). s-tile 256, d-chunk 32.
// Per-thread tile 4h x 4s (16 u64 acc = 32 regs) for occupancy.
// Warp w: heads (w>>1)*4.. ; s: ((w&1)<<5)|lane + 64j.
// Pitch 34: conflict-free LDS.64 (lane stride 34 = 2 mod 32 -> all banks/phase).
__global__ void __launch_bounds__(256) k_scores_copyk(
    const float* __restrict__ past_key, const float* __restrict__ key,
    float* __restrict__ comb_key) {
    const int b = blockIdx.y;
    const int s0 = blockIdx.x * 256;
    const int t = threadIdx.x;
    const int warp = t >> 5, lane = t & 31;
    const int hbase = (warp >> 1) * 4;
    const int sgrp = ((warp & 1) << 5) | lane;   // 0..63
    __shared__ float Rt[HH][34];
    __shared__ float CKt[256][34];
    u64 acc[4][4] = {};

    const int lrow = t >> 3;           // 0..31
    const int lc   = (t & 7) * 4;      // 0,4,..28

    for (int dc = 0; dc < DD; dc += 32) {
        __syncthreads();
        // R tile: 16 x 32 (first 128 threads)
        if (t < 128) {
            int rr = t >> 3;
            float4 v = *(const float4*)&g_R[(size_t)(b * HH + rr) * DD + dc + lc];
            *(float2*)&Rt[rr][lc]     = make_float2(v.x, v.y);
            *(float2*)&Rt[rr][lc + 2] = make_float2(v.z, v.w);
        }
        // CK tile: 256 x 32, coalesced (8 threads x float4 = 128B per row),
        // write-through to comb_key
        #pragma unroll
        for (int p = 0; p < 8; p++) {
            int row = p * 32 + lrow;
            int s = s0 + row;
            float4 v;
            if (s < SS) {
                v = *(const float4*)&past_key[((size_t)b * SS + s) * DD + dc + lc];
                *(float4*)&comb_key[((size_t)b * SK + s) * DD + dc + lc] = v;
            } else if (s == SS) {
                v = *(const float4*)&key[(size_t)b * DD + dc + lc];
                *(float4*)&comb_key[((size_t)b * SK + s) * DD + dc + lc] = v;
            } else {
                v = make_float4(0.f, 0.f, 0.f, 0.f);
            }
            *(float2*)&CKt[row][lc]     = make_float2(v.x, v.y);
            *(float2*)&CKt[row][lc + 2] = make_float2(v.z, v.w);
        }
        __syncthreads();
        // GEMM over this d-chunk: 16 dd-pairs
        #pragma unroll
        for (int dd = 0; dd < 32; dd += 2) {
            u64 r2[4], c2[4];
            #pragma unroll
            for (int i = 0; i < 4; i++) r2[i] = *(const u64*)&Rt[hbase + i][dd];
            #pragma unroll
            for (int j = 0; j < 4; j++) c2[j] = *(const u64*)&CKt[sgrp + 64 * j][dd];
            #pragma unroll
            for (int i = 0; i < 4; i++) {
                #pragma unroll
                for (int j = 0; j < 4; j++) ffma2(acc[i][j], r2[i], c2[j]);
            }
        }
    }
    #pragma unroll
    for (int i = 0; i < 4; i++) {
        #pragma unroll
        for (int j = 0; j < 4; j++) {
            int s = s0 + sgrp + 64 * j;
            if (s < SK) {
                float2 f = unpack2(acc[i][j]);
                g_sc[(size_t)(b * HH + hbase + i) * SP + s] = f.x + f.y;
            }
        }
    }
}

// ---------------- C: softmax, 512 threads ----------------
__global__ void k_softmax() {
    int b = blockIdx.x >> 4, h = blockIdx.x & 15;
    float* sc = g_sc + (size_t)(b * HH + h) * SP;
    __shared__ float buf[SK];
    __shared__ float red[512];
    int t = threadIdx.x;
    float m = -1e30f;
    for (int i = t; i < SK; i += 512) { float v = sc[i]; buf[i] = v; m = fmaxf(m, v); }
    red[t] = m; __syncthreads();
    for (int o = 256; o; o >>= 1) { if (t < o) red[t] = fmaxf(red[t], red[t + o]); __syncthreads(); }
    m = red[0]; __syncthreads();
    float s = 0.f;
    for (int i = t; i < SK; i += 512) { float e = __expf(buf[i] - m); buf[i] = e; s += e; }
    red[t] = s; __syncthreads();
    for (int o = 256; o; o >>= 1) { if (t < o) red[t] += red[t + o]; __syncthreads(); }
    float inv = 1.f / red[0];
    __syncthreads();
    for (int i = t; i < SK; i += 512) sc[i] = buf[i] * inv;
}

// ---------------- D: fused copy-V + weighted sum (known good) ---------------
__global__ void __launch_bounds__(256) k_wsum_copyv(
    const float* __restrict__ past_value, const float* __restrict__ value,
    float* __restrict__ comb_value) {
    int b = blockIdx.y;
    int s0 = blockIdx.x * 256;
    int t = threadIdx.x;
    __shared__ float At[HH][256];
    #pragma unroll
    for (int p = 0; p < 16; p++) {
        int idx = p * 256 + t;
        int h = idx >> 8, sl = idx & 255;
        int s = s0 + sl;
        At[h][sl] = (s < SK) ? g_sc[(size_t)(b * HH + h) * SP + s] : 0.f;
    }
    __syncthreads();
    float4 acc[HH];
    #pragma unroll
    for (int h = 0; h < HH; h++) acc[h] = make_float4(0.f, 0.f, 0.f, 0.f);
    const int d = 4 * t;
    const bool fast = (s0 + 256 <= SS);

    for (int sg = 0; sg < 256; sg += 4) {
        float4 cv[4];
        #pragma unroll
        for (int j = 0; j < 4; j++) {
            int s = s0 + sg + j;
            if (fast || s < SS) {
                cv[j] = *(const float4*)&past_value[((size_t)b * SS + s) * DD + d];
                *(float4*)&comb_value[((size_t)b * SK + s) * DD + d] = cv[j];
            } else if (s == SS) {
                cv[j] = *(const float4*)&value[b * DD + d];
                *(float4*)&comb_value[((size_t)b * SK + s) * DD + d] = cv[j];
            } else {
                cv[j] = make_float4(0.f, 0.f, 0.f, 0.f);
            }
        }
        #pragma unroll
        for (int h = 0; h < HH; h++) {
            float4 a = *(const float4*)&At[h][sg];
            acc[h].x += a.x * cv[0].x + a.y * cv[1].x + a.z * cv[2].x + a.w * cv[3].x;
            acc[h].y += a.x * cv[0].y + a.y * cv[1].y + a.z * cv[2].y + a.w * cv[3].y;
            acc[h].z += a.x * cv[0].z + a.y * cv[1].z + a.z * cv[2].z + a.w * cv[3].z;
            acc[h].w += a.x * cv[0].w + a.y * cv[1].w + a.z * cv[2].w + a.w * cv[3].w;
        }
    }
    #pragma unroll
    for (int h = 0; h < HH; h++) {
        float* w = &g_W[(size_t)(b * HH + h) * DD + d];
        atomicAdd(w + 0, acc[h].x);
        atomicAdd(w + 1, acc[h].y);
        atomicAdd(w + 2, acc[h].z);
        atomicAdd(w + 3, acc[h].w);
    }
}

// ---------------- E1: ctx ----------------
__global__ void k_ctxproj(const float* __restrict__ w_in,
                          const float* __restrict__ b_in) {
    int o = blockIdx.x * 8 + (threadIdx.x >> 5);
    int lane = threadIdx.x & 31;
    int b = o & 15, i = o >> 4, h = i >> 6;
    const float* wv = w_in + (size_t)(2 * DD + i) * DD;
    const float* Wb = g_W + (size_t)(b * HH + h) * DD;
    float acc = 0.f;
    #pragma unroll
    for (int k = lane * 4; k < DD; k += 128) {
        float4 a = *(const float4*)(wv + k);
        float4 w = *(const float4*)(Wb + k);
        acc += a.x * w.x + a.y * w.y + a.z * w.z + a.w * w.w;
    }
    #pragma unroll
    for (int off = 16; off; off >>= 1) acc += __shfl_down_sync(0xffffffffu, acc, off);
    if (lane == 0) g_ctx[b * DD + i] = acc + b_in[2 * DD + i];
}

// ---------------- E2: out ----------------
__global__ void k_outproj(const float* __restrict__ w_out,
                          const float* __restrict__ b_out,
                          float* __restrict__ out) {
    int o = blockIdx.x * 8 + (threadIdx.x >> 5);
    int lane = threadIdx.x & 31;
    int b = o & 15, i = o >> 4;
    const float* wr = w_out + (size_t)i * DD;
    const float* cx = g_ctx + b * DD;
    float acc = 0.f;
    #pragma unroll
    for (int k = lane * 4; k < DD; k += 128) {
        float4 a = *(const float4*)(wr + k);
        float4 w = *(const float4*)(cx + k);
        acc += a.x * w.x + a.y * w.y + a.z * w.z + a.w * w.w;
    }
    #pragma unroll
    for (int off = 16; off; off >>= 1) acc += __shfl_down_sync(0xffffffffu, acc, off);
    if (lane == 0) out[b * DD + i] = acc + b_out[i];
}

// ---------------- launch ----------------
extern "C" void kernel_launch(void* const* d_in, const int* in_sizes, int n_in,
                              void* d_out, int out_size) {
    const float* query      = (const float*)d_in[0];
    const float* key        = (const float*)d_in[1];
    const float* value      = (const float*)d_in[2];
    const float* past_key   = (const float*)d_in[3];
    const float* past_value = (const float*)d_in[4];
    const float* w_in       = (const float*)d_in[5];
    const float* b_in       = (const float*)d_in[6];
    const float* w_out      = (const float*)d_in[7];
    const float* b_out      = (const float*)d_in[8];

    float* out        = (float*)d_out;
    float* comb_key   = out + (size_t)BB * DD;
    float* comb_value = comb_key + (size_t)BB * SK * DD;

    k_dummy<<<1, 32>>>();
    k_qproj<<<2048, 256>>>(query, w_in, b_in);
    k_rproj<<<256, 256>>>(w_in);
    k_scores_copyk<<<dim3(17, 16), 256>>>(past_key, key, comb_key);
    k_softmax<<<256, 512>>>();
    k_wsum_copyv<<<dim3(17, 16), 256>>>(past_value, value, comb_value);
    k_ctxproj<<<2048, 256>>>(w_in, b_in);
    k_outproj<<<2048, 256>>>(w_out, b_out, out);
}